// round 16
// baseline (speedup 1.0000x reference)
#include <cuda_runtime.h>
#include <cuda_bf16.h>
#include <math_constants.h>

#define BB 8
#define NP 2048
#define KK 20
#define BN (BB*NP)
#define EPSV 1e-5f
#define SLOPEV 0.2f
#define CAP 192
#define DELTA 0.015f

// ---------------- scratch ----------------
__device__ float2 g_xx[BN];
__device__ int    g_idx[BN*KK];
__device__ float  g_pd[(size_t)BN*NP];
__device__ float  g_x1[BN*64];
__device__ float  g_x2[BN*64];
__device__ float  g_x3[BN*128];
__device__ float  g_x4[BN*256];
__device__ float  g_m[BN*256];
__device__ float  g_m5[BB*1024];
__device__ double g_sum[1024];
__device__ double g_sumsq[1024];
__device__ float2 g_bn[1024];
__device__ float  g_W1t[6*64];
__device__ float  g_W2t[128*64];
__device__ float  g_W3t[128*128];
__device__ float  g_W4t[256*256];
__device__ float  g_W5t[512*1024];

// ---------------- helpers ----------------
__device__ __forceinline__ unsigned long long knn_key(float v, unsigned j) {
    int i = __float_as_int(v);
    unsigned u = (i >= 0) ? ((unsigned)i | 0x80000000u) : ~((unsigned)i);
    return ((unsigned long long)u << 32) | (unsigned long long)(0xFFFFFFFFu - j);
}
__device__ __forceinline__ float key_pd(unsigned long long k) {
    unsigned u = (unsigned)(k >> 32);
    int i = (u & 0x80000000u) ? (int)(u & 0x7FFFFFFFu) : (int)(~u);
    return __int_as_float(i);
}
__device__ __forceinline__ int key_idx(unsigned long long k) {
    return (int)(0xFFFFFFFFu - (unsigned)(k & 0xFFFFFFFFull));
}
__device__ __forceinline__ unsigned long long warp_max_bfly(unsigned long long v) {
    #pragma unroll
    for (int s = 16; s > 0; s >>= 1) {
        unsigned long long o = __shfl_xor_sync(0xFFFFFFFFu, v, s);
        v = (o > v) ? o : v;
    }
    return v;
}
__device__ __forceinline__ void atomicMaxFloat(float* addr, float val) {
    int* ia = (int*)addr;
    int old = *ia;
    while (__int_as_float(old) < val) {
        int assumed = old;
        old = atomicCAS(ia, assumed, __float_as_int(val));
        if (old == assumed) break;
    }
}
__device__ __forceinline__ void two_sum(float a, float b, float& s, float& e) {
    s = __fadd_rn(a, b);
    float bb = __fsub_rn(s, a);
    e = __fadd_rn(__fsub_rn(a, __fsub_rn(s, bb)), __fsub_rn(b, bb));
}
__device__ __forceinline__ void kah(float a, float b, float& sa, float& ca, float& ea) {
    float p = __fmul_rn(a, b);
    ea = __fadd_rn(ea, __fmaf_rn(a, b, -p));
    float y = __fsub_rn(p, ca);
    float t = __fadd_rn(sa, y);
    ca = __fsub_rn(__fsub_rn(t, sa), y);
    sa = t;
}
__device__ __forceinline__ float pd_tail(float H, float L, float2 xq, float2 xj) {
    float th = __fmul_rn(2.f, H), tl = __fmul_rn(2.f, L);
    float sA, eA;
    two_sum(th, -xq.x, sA, eA);
    eA = __fadd_rn(eA, __fsub_rn(tl, xq.y));
    float th2 = __fadd_rn(sA, eA);
    float tl2 = __fsub_rn(eA, __fsub_rn(th2, sA));
    float sB, eB;
    two_sum(th2, -xj.x, sB, eB);
    eB = __fadd_rn(eB, __fsub_rn(tl2, xj.y));
    return __fadd_rn(sB, eB);
}
__device__ __forceinline__ float pd_finalize(float s0, float s1, float s2, float s3,
                                             float c0, float c1, float c2, float c3,
                                             float e0, float e1, float e2, float e3,
                                             float2 xq, float2 xj) {
    float h01, l01, h23, l23, H, L;
    two_sum(s0, s1, h01, l01);
    two_sum(s2, s3, h23, l23);
    two_sum(h01, h23, H, L);
    float elo = __fadd_rn(__fadd_rn(__fadd_rn(e0, e1), __fadd_rn(e2, e3)),
                __fsub_rn(__fadd_rn(__fadd_rn(l01, l23), L),
                          __fadd_rn(__fadd_rn(c0, c1), __fadd_rn(c2, c3))));
    return pd_tail(H, elo, xq, xj);
}

// ---------------- transpose ----------------
__global__ void transpose_kernel(const float* __restrict__ in, float* __restrict__ out,
                                 int O, int I) {
    int idx = blockIdx.x * blockDim.x + threadIdx.x;
    if (idx >= O * I) return;
    int o = idx / I, c = idx % I;
    out[c * O + o] = in[idx];
}

// ---------------- reset kernels ----------------
__global__ void reset_stats_kernel() {
    int i = blockIdx.x * blockDim.x + threadIdx.x;
    if (i < 1024) { g_sum[i] = 0.0; g_sumsq[i] = 0.0; }
}
__global__ void reset_m5_kernel() {
    int i = blockIdx.x * blockDim.x + threadIdx.x;
    if (i < 1024) { g_sum[i] = 0.0; g_sumsq[i] = 0.0; }
    if (i < BB * 1024) g_m5[i] = -CUDART_INF_F;
}

// ---------------- BN fold ----------------
__global__ void bnparam_kernel(const float* __restrict__ gamma,
                               const float* __restrict__ beta, double Minv) {
    int o = threadIdx.x + blockIdx.x * blockDim.x;
    double mean = g_sum[o] * Minv;
    double var = g_sumsq[o] * Minv - mean * mean;
    double scale = 1.0 / sqrt(var + (double)EPSV);
    double A = (double)gamma[o] * scale;
    double B = (double)beta[o] - mean * A;
    g_bn[o] = make_float2((float)A, (float)B);
}

// ---------------- squared norms ----------------
template<int C>
__global__ void xx_kernel(const float* __restrict__ x) {
    int p = blockIdx.x * blockDim.x + threadIdx.x;
    if (p >= BN) return;
    const float* r = x + (size_t)p * C;
    double s = 0.0;
    #pragma unroll 4
    for (int c = 0; c < C; c++) { double v = (double)r[c]; s = fma(v, v, s); }
    float hi = (float)s;
    float lo = (float)(s - (double)hi);
    g_xx[p] = make_float2(hi, lo);
}

// ---------------- phase A: approx pd ----------------
template<int C>
__global__ __launch_bounds__(256) void pda_kernel(const float* __restrict__ x) {
    constexpr int CK = 64, CP = CK + 4;
    __shared__ __align__(16) float sQ[64][CP];
    __shared__ __align__(16) float sC[64][CP];
    const int tid = threadIdx.x;
    const int ty = tid >> 4, tx = tid & 15;
    const int b = blockIdx.z;
    const int q0 = blockIdx.x * 64;
    const int jt0 = blockIdx.y * 8;
    const float* xb = x + (size_t)b * NP * C;

    float xq[4];
    #pragma unroll
    for (int i = 0; i < 4; i++) xq[i] = g_xx[b * NP + q0 + ty * 4 + i].x;

    for (int jt = jt0; jt < jt0 + 8; jt++) {
        float acc[16];
        #pragma unroll
        for (int a = 0; a < 16; a++) acc[a] = 0.f;

        #pragma unroll
        for (int ch = 0; ch < C / CK; ch++) {
            __syncthreads();
            for (int idx = tid; idx < 64 * CK; idx += 256) {
                int row = idx >> 6, col = idx & 63;
                sQ[row][col] = xb[(size_t)(q0 + row) * C + ch * CK + col];
                sC[row][col] = xb[(size_t)(jt * 64 + row) * C + ch * CK + col];
            }
            __syncthreads();
            #pragma unroll 4
            for (int cc = 0; cc < CK; cc += 4) {
                float4 qv[4], cv[4];
                #pragma unroll
                for (int i = 0; i < 4; i++) {
                    qv[i] = *reinterpret_cast<const float4*>(&sQ[ty * 4 + i][cc]);
                    cv[i] = *reinterpret_cast<const float4*>(&sC[tx * 4 + i][cc]);
                }
                #pragma unroll
                for (int i = 0; i < 4; i++) {
                    #pragma unroll
                    for (int j2 = 0; j2 < 4; j2++) {
                        int a = i * 4 + j2;
                        acc[a] = __fmaf_rn(qv[i].x, cv[j2].x, acc[a]);
                        acc[a] = __fmaf_rn(qv[i].y, cv[j2].y, acc[a]);
                        acc[a] = __fmaf_rn(qv[i].z, cv[j2].z, acc[a]);
                        acc[a] = __fmaf_rn(qv[i].w, cv[j2].w, acc[a]);
                    }
                }
            }
        }
        #pragma unroll
        for (int j2 = 0; j2 < 4; j2++) {
            float xj = g_xx[b * NP + jt * 64 + tx * 4 + j2].x;
            #pragma unroll
            for (int i = 0; i < 4; i++) {
                float pd = (2.f * acc[i * 4 + j2] - xq[i]) - xj;
                g_pd[(size_t)(b * NP + q0 + ty * 4 + i) * NP + jt * 64 + tx * 4 + j2] = pd;
            }
        }
    }
}

// ---------------- phase B: select + refine ----------------
template<int C>
__global__ __launch_bounds__(256) void topk_refine_kernel(const float* __restrict__ x) {
    __shared__ unsigned long long swk[8][KK];
    __shared__ unsigned long long rkey[CAP];
    __shared__ int  cand[CAP];
    __shared__ int  scnt;
    __shared__ float sT;
    __shared__ __align__(16) float q[(C + 3) & ~3];
    const int tid = threadIdx.x;
    const int lane = tid & 31, warp = tid >> 5;
    const int pq = blockIdx.x;
    const int b = pq / NP, n = pq % NP;
    const float* xb = x + (size_t)b * NP * C;

    for (int c = tid; c < C; c += 256) q[c] = xb[(size_t)n * C + c];
    if (tid == 0) scnt = 0;
    if (tid < CAP) rkey[tid] = 0ULL;

    const float* pdrow = g_pd + (size_t)pq * NP;
    unsigned long long key[8];
    #pragma unroll
    for (int t = 0; t < 8; t++) {
        int j = tid + t * 256;
        key[t] = knn_key(pdrow[j], (unsigned)j);
    }
    #pragma unroll
    for (int a = 1; a < 8; a++) {
        unsigned long long kk = key[a];
        int p2 = a - 1;
        while (p2 >= 0 && key[p2] < kk) { key[p2 + 1] = key[p2]; p2--; }
        key[p2 + 1] = kk;
    }

    {
        int ptr = 0;
        #pragma unroll 1
        for (int sel = 0; sel < KK; sel++) {
            unsigned long long v = (ptr < 8) ? key[ptr] : 0ULL;
            unsigned long long m = warp_max_bfly(v);
            if (ptr < 8 && key[ptr] == m) ptr++;
            if (lane == 0) swk[warp][sel] = m;
        }
    }
    __syncthreads();

    if (warp == 0) {
        unsigned long long mk[5];
        #pragma unroll
        for (int i = 0; i < 5; i++) mk[i] = ((unsigned long long*)swk)[lane * 5 + i];
        unsigned long long m = 0;
        #pragma unroll 1
        for (int sel = 0; sel < KK; sel++) {
            unsigned long long lm = 0; int li = -1;
            #pragma unroll
            for (int i = 0; i < 5; i++) if (mk[i] > lm) { lm = mk[i]; li = i; }
            m = warp_max_bfly(lm);
            if (lm == m && li >= 0) mk[li] = 0ULL;
        }
        if (lane == 0) sT = key_pd(m) - DELTA;
    }
    __syncthreads();

    {
        float T = sT;
        #pragma unroll 1
        for (int t = 0; t < 8; t++) {
            if (key_pd(key[t]) < T) break;
            int pos = atomicAdd(&scnt, 1);
            if (pos < CAP) cand[pos] = key_idx(key[t]);
        }
    }
    __syncthreads();
    int cnt = min(scnt, CAP);

    float2 xq = g_xx[pq];
    if (tid < cnt) {
        int j = cand[tid];
        const float4* r4 = reinterpret_cast<const float4*>(xb + (size_t)j * C);
        const float4* q4 = reinterpret_cast<const float4*>(q);
        float s0 = 0.f, s1 = 0.f, s2 = 0.f, s3 = 0.f;
        float c0 = 0.f, c1 = 0.f, c2 = 0.f, c3 = 0.f;
        float e0 = 0.f, e1 = 0.f, e2 = 0.f, e3 = 0.f;
        #pragma unroll 4
        for (int c = 0; c < C / 4; c++) {
            float4 rv = r4[c], qv = q4[c];
            kah(qv.x, rv.x, s0, c0, e0);
            kah(qv.y, rv.y, s1, c1, e1);
            kah(qv.z, rv.z, s2, c2, e2);
            kah(qv.w, rv.w, s3, c3, e3);
        }
        float2 xj = g_xx[b * NP + j];
        float pd = pd_finalize(s0, s1, s2, s3, c0, c1, c2, c3, e0, e1, e2, e3, xq, xj);
        rkey[tid] = knn_key(pd, (unsigned)j);
    }
    __syncthreads();

    if (warp == 0) {
        unsigned long long mk[6];
        #pragma unroll
        for (int i = 0; i < 6; i++) mk[i] = rkey[lane * 6 + i];
        int* out = g_idx + (size_t)pq * KK;
        #pragma unroll 1
        for (int sel = 0; sel < KK; sel++) {
            unsigned long long lm = 0; int li = -1;
            #pragma unroll
            for (int i = 0; i < 6; i++) if (mk[i] > lm) { lm = mk[i]; li = i; }
            unsigned long long m = warp_max_bfly(lm);
            if (lm == m && li >= 0) mk[li] = 0ULL;
            if (lane == 0) out[sel] = key_idx(m);
        }
    }
}

// ---------------- layer-1 knn (C=3) ----------------
__global__ __launch_bounds__(256) void knn3_kernel(const float* __restrict__ x) {
    __shared__ unsigned long long swk[8][KK];
    const int tid = threadIdx.x;
    const int lane = tid & 31, warp = tid >> 5;
    const int b = blockIdx.x / NP;
    const int n = blockIdx.x % NP;
    const float* xb = x + (size_t)b * NP * 3;

    float q0 = xb[(size_t)n * 3 + 0], q1 = xb[(size_t)n * 3 + 1], q2 = xb[(size_t)n * 3 + 2];
    float2 xxi = g_xx[b * NP + n];
    const float2* xxb = g_xx + b * NP;

    unsigned long long key[8];
    #pragma unroll
    for (int t = 0; t < 8; t++) {
        int j = tid + t * 256;
        const float* r = xb + (size_t)j * 3;
        float r0 = r[0], r1 = r[1], r2 = r[2];
        float p0 = __fmul_rn(q0, r0), e0 = __fmaf_rn(q0, r0, -p0);
        float p1 = __fmul_rn(q1, r1), e1 = __fmaf_rn(q1, r1, -p1);
        float p2 = __fmul_rn(q2, r2), e2 = __fmaf_rn(q2, r2, -p2);
        float t1, u1, H, u2;
        two_sum(p0, p1, t1, u1);
        two_sum(t1, p2, H, u2);
        float L = __fadd_rn(__fadd_rn(__fadd_rn(e0, e1), e2), __fadd_rn(u1, u2));
        float pd = pd_tail(H, L, xxi, xxb[j]);
        key[t] = knn_key(pd, (unsigned)j);
    }
    #pragma unroll
    for (int a = 1; a < 8; a++) {
        unsigned long long kk = key[a];
        int p2 = a - 1;
        while (p2 >= 0 && key[p2] < kk) { key[p2 + 1] = key[p2]; p2--; }
        key[p2 + 1] = kk;
    }

    {
        int ptr = 0;
        #pragma unroll 1
        for (int sel = 0; sel < KK; sel++) {
            unsigned long long v = (ptr < 8) ? key[ptr] : 0ULL;
            unsigned long long m = warp_max_bfly(v);
            if (ptr < 8 && key[ptr] == m) ptr++;
            if (lane == 0) swk[warp][sel] = m;
        }
    }
    __syncthreads();

    if (warp == 0) {
        unsigned long long mk[5];
        #pragma unroll
        for (int i = 0; i < 5; i++) mk[i] = ((unsigned long long*)swk)[lane * 5 + i];
        int* out = g_idx + (size_t)(b * NP + n) * KK;
        #pragma unroll 1
        for (int sel = 0; sel < KK; sel++) {
            unsigned long long lm = 0; int li = -1;
            #pragma unroll
            for (int i = 0; i < 5; i++) if (mk[i] > lm) { lm = mk[i]; li = i; }
            unsigned long long m = warp_max_bfly(lm);
            if (lm == m && li >= 0) mk[li] = 0ULL;
            if (lane == 0) out[sel] = key_idx(m);
        }
    }
}

// ---------------- conv layer 1 (C=3, small; old style) ----------------
__global__ void conv1_kernel(const float* __restrict__ xin, const float* __restrict__ Wt,
                             float* __restrict__ m) {
    constexpr int C = 3, O = 64, TPB = 128;
    __shared__ float xc[4];
    __shared__ float D[KK][4];
    __shared__ int nidx[KK];
    const int tid = threadIdx.x;
    const int b = blockIdx.x / NP;
    const int n = blockIdx.x % NP;
    const float* xb = xin + (size_t)b * NP * C;

    if (tid < C) xc[tid] = xb[(size_t)n * C + tid];
    if (tid < KK) nidx[tid] = g_idx[(size_t)(b * NP + n) * KK + tid];
    __syncthreads();
    for (int e = tid; e < KK * C; e += TPB) {
        int k = e / C, c = e % C;
        D[k][c] = xb[(size_t)nidx[k] * C + c] - xc[c];
    }
    __syncthreads();

    if (tid < O) {
        int o = tid;
        float cx = 0.f;
        #pragma unroll
        for (int c = 0; c < C; c++) cx += Wt[(C + c) * O + o] * xc[c];
        float acc[KK];
        #pragma unroll
        for (int k = 0; k < KK; k++) acc[k] = cx;
        #pragma unroll
        for (int c = 0; c < C; c++) {
            float w = Wt[c * O + o];
            #pragma unroll
            for (int k = 0; k < KK; k++) acc[k] += w * D[k][c];
        }
        float mv = -CUDART_INF_F, s = 0.f, s2 = 0.f;
        #pragma unroll
        for (int k = 0; k < KK; k++) {
            mv = fmaxf(mv, acc[k]);
            s = __fadd_rn(s, acc[k]);
            s2 = __fmaf_rn(acc[k], acc[k], s2);
        }
        m[(size_t)(b * NP + n) * O + o] = mv;
        atomicAdd(&g_sum[o], (double)s);
        atomicAdd(&g_sumsq[o], (double)s2);
    }
}

// ---------------- edge conv (layers 2-4): register-tiled, non-broadcast ----------------
// blockDim = O. thread: oi = tid>>2 (4 outputs), ki = tid&3 (5 k's).
template<int C, int O>
__global__ __launch_bounds__(256) void conv_kernel2(const float* __restrict__ xin,
                                                    const float* __restrict__ Wt,
                                                    float* __restrict__ m) {
    constexpr int KP = 21;  // padded k dim (21 coprime 32 -> conflict-free build)
    __shared__ float xc[C];
    __shared__ float sDT[C][KP];
    __shared__ int nidx[KK];
    const int tid = threadIdx.x;
    const int b = blockIdx.x / NP;
    const int n = blockIdx.x % NP;
    const float* xb = xin + (size_t)b * NP * C;

    for (int c = tid; c < C; c += O) xc[c] = xb[(size_t)n * C + c];
    if (tid < KK) nidx[tid] = g_idx[(size_t)(b * NP + n) * KK + tid];
    __syncthreads();
    for (int e = tid; e < KK * C; e += O) {
        int k = e / C, c = e % C;   // consecutive threads -> consecutive c (coalesced read)
        sDT[c][k] = xb[(size_t)nidx[k] * C + c] - xc[c];
    }
    __syncthreads();

    const int oi = tid >> 2, ki = tid & 3;
    const int o0 = oi * 4;
    const int kb = ki * 5;

    // cx for the 4 outputs
    float cx[4] = {0.f, 0.f, 0.f, 0.f};
    for (int c = 0; c < C; c++) {
        float xcv = xc[c];
        float4 w = *reinterpret_cast<const float4*>(Wt + (size_t)(C + c) * O + o0);
        cx[0] = __fmaf_rn(w.x, xcv, cx[0]);
        cx[1] = __fmaf_rn(w.y, xcv, cx[1]);
        cx[2] = __fmaf_rn(w.z, xcv, cx[2]);
        cx[3] = __fmaf_rn(w.w, xcv, cx[3]);
    }

    // main: acc[i][t] = sum_c Wd[c][o0+i] * D[c][kb+t]
    float acc[4][5];
    #pragma unroll
    for (int i = 0; i < 4; i++)
        #pragma unroll
        for (int t = 0; t < 5; t++) acc[i][t] = 0.f;

    for (int c = 0; c < C; c++) {
        float4 w = *reinterpret_cast<const float4*>(Wt + (size_t)c * O + o0);
        float d0 = sDT[c][kb + 0];
        float d1 = sDT[c][kb + 1];
        float d2 = sDT[c][kb + 2];
        float d3 = sDT[c][kb + 3];
        float d4 = sDT[c][kb + 4];
        acc[0][0] = __fmaf_rn(w.x, d0, acc[0][0]);
        acc[0][1] = __fmaf_rn(w.x, d1, acc[0][1]);
        acc[0][2] = __fmaf_rn(w.x, d2, acc[0][2]);
        acc[0][3] = __fmaf_rn(w.x, d3, acc[0][3]);
        acc[0][4] = __fmaf_rn(w.x, d4, acc[0][4]);
        acc[1][0] = __fmaf_rn(w.y, d0, acc[1][0]);
        acc[1][1] = __fmaf_rn(w.y, d1, acc[1][1]);
        acc[1][2] = __fmaf_rn(w.y, d2, acc[1][2]);
        acc[1][3] = __fmaf_rn(w.y, d3, acc[1][3]);
        acc[1][4] = __fmaf_rn(w.y, d4, acc[1][4]);
        acc[2][0] = __fmaf_rn(w.z, d0, acc[2][0]);
        acc[2][1] = __fmaf_rn(w.z, d1, acc[2][1]);
        acc[2][2] = __fmaf_rn(w.z, d2, acc[2][2]);
        acc[2][3] = __fmaf_rn(w.z, d3, acc[2][3]);
        acc[2][4] = __fmaf_rn(w.z, d4, acc[2][4]);
        acc[3][0] = __fmaf_rn(w.w, d0, acc[3][0]);
        acc[3][1] = __fmaf_rn(w.w, d1, acc[3][1]);
        acc[3][2] = __fmaf_rn(w.w, d2, acc[3][2]);
        acc[3][3] = __fmaf_rn(w.w, d3, acc[3][3]);
        acc[3][4] = __fmaf_rn(w.w, d4, acc[3][4]);
    }

    // per-output reduce over 5 local k's, then across 4 ki lanes (xor 1,2)
    float M[4], S[4], Q[4];
    #pragma unroll
    for (int i = 0; i < 4; i++) {
        float mv = acc[i][0], s = acc[i][0], q = acc[i][0] * acc[i][0];
        #pragma unroll
        for (int t = 1; t < 5; t++) {
            mv = fmaxf(mv, acc[i][t]);
            s = __fadd_rn(s, acc[i][t]);
            q = __fmaf_rn(acc[i][t], acc[i][t], q);
        }
        #pragma unroll
        for (int sft = 1; sft <= 2; sft <<= 1) {
            mv = fmaxf(mv, __shfl_xor_sync(0xFFFFFFFFu, mv, sft));
            s  = __fadd_rn(s, __shfl_xor_sync(0xFFFFFFFFu, s, sft));
            q  = __fadd_rn(q, __shfl_xor_sync(0xFFFFFFFFu, q, sft));
        }
        M[i] = mv; S[i] = s; Q[i] = q;
    }

    if (ki == 0) {
        float mvout[4];
        float ssum = 0.f, qsum = 0.f;  // dummy init removed below
        #pragma unroll
        for (int i = 0; i < 4; i++) {
            float c1 = cx[i];
            mvout[i] = M[i] + c1;
            // s over h: S + 20*cx ; q over h: Q + 2*cx*S + 20*cx^2
            float sh = __fadd_rn(S[i], 20.f * c1);
            float qh = __fadd_rn(Q[i], __fmaf_rn(2.f * c1, S[i], 20.f * c1 * c1));
            atomicAdd(&g_sum[o0 + i], (double)sh);
            atomicAdd(&g_sumsq[o0 + i], (double)qh);
        }
        (void)ssum; (void)qsum;
        *reinterpret_cast<float4*>(m + (size_t)(b * NP + n) * O + o0) =
            make_float4(mvout[0], mvout[1], mvout[2], mvout[3]);
    }
}

// ---------------- post: xout = lrelu(m*A + B) ----------------
template<int O>
__global__ void post_kernel(const float* __restrict__ m, float* __restrict__ xout) {
    int i = blockIdx.x * blockDim.x + threadIdx.x;
    if (i >= BN * O) return;
    int o = i % O;
    float2 ab = g_bn[o];
    float h = __fmaf_rn(m[i], ab.x, ab.y);
    xout[i] = (h >= 0.f) ? h : SLOPEV * h;
}

// ---------------- conv5: register-tiled, transposed sx ----------------
// 16 points/block; thread: oi = tid>>2 (4 outputs per j-round), pi = tid&3 (4 points)
__global__ __launch_bounds__(256) void conv5_kernel() {
    constexpr int PP = 20;  // padded p dim (float4-aligned at pi*4)
    __shared__ __align__(16) float sxT[512][PP];
    const int tid = threadIdx.x;
    const int b = blockIdx.x / (NP / 16);
    const int n0 = (blockIdx.x % (NP / 16)) * 16;

    for (int e = tid; e < 16 * 512; e += 256) {
        int p = e >> 9, c = e & 511;
        size_t pn = (size_t)b * NP + n0 + p;
        float v;
        if (c < 64)       v = g_x1[pn * 64 + c];
        else if (c < 128) v = g_x2[pn * 64 + (c - 64)];
        else if (c < 256) v = g_x3[pn * 128 + (c - 128)];
        else              v = g_x4[pn * 256 + (c - 256)];
        sxT[c][p] = v;
    }
    __syncthreads();

    const int oi = tid >> 2, pi = tid & 3;

    #pragma unroll
    for (int j = 0; j < 4; j++) {
        int o0 = j * 256 + oi * 4;
        float acc[4][4];
        #pragma unroll
        for (int i = 0; i < 4; i++)
            #pragma unroll
            for (int p = 0; p < 4; p++) acc[i][p] = 0.f;

        for (int c = 0; c < 512; c++) {
            float4 w = *reinterpret_cast<const float4*>(g_W5t + (size_t)c * 1024 + o0);
            float4 d = *reinterpret_cast<const float4*>(&sxT[c][pi * 4]);
            acc[0][0] = __fmaf_rn(w.x, d.x, acc[0][0]);
            acc[0][1] = __fmaf_rn(w.x, d.y, acc[0][1]);
            acc[0][2] = __fmaf_rn(w.x, d.z, acc[0][2]);
            acc[0][3] = __fmaf_rn(w.x, d.w, acc[0][3]);
            acc[1][0] = __fmaf_rn(w.y, d.x, acc[1][0]);
            acc[1][1] = __fmaf_rn(w.y, d.y, acc[1][1]);
            acc[1][2] = __fmaf_rn(w.y, d.z, acc[1][2]);
            acc[1][3] = __fmaf_rn(w.y, d.w, acc[1][3]);
            acc[2][0] = __fmaf_rn(w.z, d.x, acc[2][0]);
            acc[2][1] = __fmaf_rn(w.z, d.y, acc[2][1]);
            acc[2][2] = __fmaf_rn(w.z, d.z, acc[2][2]);
            acc[2][3] = __fmaf_rn(w.z, d.w, acc[2][3]);
            acc[3][0] = __fmaf_rn(w.w, d.x, acc[3][0]);
            acc[3][1] = __fmaf_rn(w.w, d.y, acc[3][1]);
            acc[3][2] = __fmaf_rn(w.w, d.z, acc[3][2]);
            acc[3][3] = __fmaf_rn(w.w, d.w, acc[3][3]);
        }

        #pragma unroll
        for (int i = 0; i < 4; i++) {
            float mv = acc[i][0], s = acc[i][0], q = acc[i][0] * acc[i][0];
            #pragma unroll
            for (int p = 1; p < 4; p++) {
                mv = fmaxf(mv, acc[i][p]);
                s = __fadd_rn(s, acc[i][p]);
                q = __fmaf_rn(acc[i][p], acc[i][p], q);
            }
            #pragma unroll
            for (int sft = 1; sft <= 2; sft <<= 1) {
                mv = fmaxf(mv, __shfl_xor_sync(0xFFFFFFFFu, mv, sft));
                s  = __fadd_rn(s, __shfl_xor_sync(0xFFFFFFFFu, s, sft));
                q  = __fadd_rn(q, __shfl_xor_sync(0xFFFFFFFFu, q, sft));
            }
            if (pi == 0) {
                int o = o0 + i;
                atomicAdd(&g_sum[o], (double)s);
                atomicAdd(&g_sumsq[o], (double)q);
                atomicMaxFloat(&g_m5[b * 1024 + o], mv);
            }
        }
    }
}

// ---------------- final ----------------
__global__ void final_kernel(const float* __restrict__ g5, const float* __restrict__ b5,
                             float* __restrict__ out) {
    int b = blockIdx.x;
    int o = threadIdx.x;
    const double Minv = 1.0 / (double)(BB * NP);
    double mean = g_sum[o] * Minv;
    double var = g_sumsq[o] * Minv - mean * mean;
    float scale = (float)(1.0 / sqrt(var + (double)EPSV));
    float h = ((g_m5[b * 1024 + o] - (float)mean) * scale) * g5[o] + b5[o];
    out[b * 1024 + o] = (h >= 0.f) ? h : SLOPEV * h;
}

// ---------------- launch ----------------
extern "C" void kernel_launch(void* const* d_in, const int* in_sizes, int n_in,
                              void* d_out, int out_size) {
    const float* x  = (const float*)d_in[0];
    const float* W1 = (const float*)d_in[1];
    const float* g1 = (const float*)d_in[2];
    const float* b1 = (const float*)d_in[3];
    const float* W2 = (const float*)d_in[4];
    const float* g2 = (const float*)d_in[5];
    const float* b2 = (const float*)d_in[6];
    const float* W3 = (const float*)d_in[7];
    const float* g3 = (const float*)d_in[8];
    const float* b3 = (const float*)d_in[9];
    const float* W4 = (const float*)d_in[10];
    const float* g4 = (const float*)d_in[11];
    const float* b4 = (const float*)d_in[12];
    const float* W5 = (const float*)d_in[13];
    const float* g5 = (const float*)d_in[14];
    const float* b5 = (const float*)d_in[15];
    float* out = (float*)d_out;

    const double MinvK = 1.0 / (double)(BB * NP * KK);

    float *d_m, *d_x1, *d_x2, *d_x3, *d_x4;
    float *d_W1t, *d_W2t, *d_W3t, *d_W4t, *d_W5t;
    cudaGetSymbolAddress((void**)&d_m, g_m);
    cudaGetSymbolAddress((void**)&d_x1, g_x1);
    cudaGetSymbolAddress((void**)&d_x2, g_x2);
    cudaGetSymbolAddress((void**)&d_x3, g_x3);
    cudaGetSymbolAddress((void**)&d_x4, g_x4);
    cudaGetSymbolAddress((void**)&d_W1t, g_W1t);
    cudaGetSymbolAddress((void**)&d_W2t, g_W2t);
    cudaGetSymbolAddress((void**)&d_W3t, g_W3t);
    cudaGetSymbolAddress((void**)&d_W4t, g_W4t);
    cudaGetSymbolAddress((void**)&d_W5t, g_W5t);

    transpose_kernel<<<(64 * 6 + 255) / 256, 256>>>(W1, d_W1t, 64, 6);
    transpose_kernel<<<(64 * 128 + 255) / 256, 256>>>(W2, d_W2t, 64, 128);
    transpose_kernel<<<(128 * 128 + 255) / 256, 256>>>(W3, d_W3t, 128, 128);
    transpose_kernel<<<(256 * 256 + 255) / 256, 256>>>(W4, d_W4t, 256, 256);
    transpose_kernel<<<(1024 * 512 + 255) / 256, 256>>>(W5, d_W5t, 1024, 512);

    dim3 pdgrid(NP / 64, 4, BB);

    // ---- Layer 1 ----
    reset_stats_kernel<<<4, 256>>>();
    xx_kernel<3><<<BN / 256, 256>>>(x);
    knn3_kernel<<<BN, 256>>>(x);
    conv1_kernel<<<BN, 128>>>(x, d_W1t, d_m);
    bnparam_kernel<<<1, 64>>>(g1, b1, MinvK);
    post_kernel<64><<<(BN * 64) / 256, 256>>>(d_m, d_x1);

    // ---- Layer 2 ----
    reset_stats_kernel<<<4, 256>>>();
    xx_kernel<64><<<BN / 256, 256>>>(d_x1);
    pda_kernel<64><<<pdgrid, 256>>>(d_x1);
    topk_refine_kernel<64><<<BN, 256>>>(d_x1);
    conv_kernel2<64, 64><<<BN, 64>>>(d_x1, d_W2t, d_m);
    bnparam_kernel<<<1, 64>>>(g2, b2, MinvK);
    post_kernel<64><<<(BN * 64) / 256, 256>>>(d_m, d_x2);

    // ---- Layer 3 ----
    reset_stats_kernel<<<4, 256>>>();
    xx_kernel<64><<<BN / 256, 256>>>(d_x2);
    pda_kernel<64><<<pdgrid, 256>>>(d_x2);
    topk_refine_kernel<64><<<BN, 256>>>(d_x2);
    conv_kernel2<64, 128><<<BN, 128>>>(d_x2, d_W3t, d_m);
    bnparam_kernel<<<1, 128>>>(g3, b3, MinvK);
    post_kernel<128><<<(BN * 128) / 256, 256>>>(d_m, d_x3);

    // ---- Layer 4 ----
    reset_stats_kernel<<<4, 256>>>();
    xx_kernel<128><<<BN / 256, 256>>>(d_x3);
    pda_kernel<128><<<pdgrid, 256>>>(d_x3);
    topk_refine_kernel<128><<<BN, 256>>>(d_x3);
    conv_kernel2<128, 256><<<BN, 256>>>(d_x3, d_W4t, d_m);
    bnparam_kernel<<<1, 256>>>(g4, b4, MinvK);
    post_kernel<256><<<(BN * 256) / 256, 256>>>(d_m, d_x4);

    // ---- conv5 + global max ----
    reset_m5_kernel<<<32, 256>>>();
    conv5_kernel<<<BB * (NP / 16), 256>>>();
    final_kernel<<<BB, 1024>>>(g5, b5, out);
}

// round 17
// speedup vs baseline: 1.1126x; 1.1126x over previous
#include <cuda_runtime.h>
#include <cuda_bf16.h>
#include <math_constants.h>

#define BB 8
#define NP 2048
#define KK 20
#define BN (BB*NP)
#define EPSV 1e-5f
#define SLOPEV 0.2f
#define CAP 192
#define DELTA 0.015f

// ---------------- scratch ----------------
__device__ float2 g_xx[BN];
__device__ int    g_idx[BN*KK];
__device__ float  g_pd[(size_t)BN*NP];
__device__ float  g_x1[BN*64];
__device__ float  g_x2[BN*64];
__device__ float  g_x3[BN*128];
__device__ float  g_x4[BN*256];
__device__ float  g_m[BN*256];
__device__ float  g_m5[BB*1024];
__device__ double g_sum[1024];
__device__ double g_sumsq[1024];
__device__ float2 g_bn[1024];
__device__ float  g_W1t[6*64];
__device__ float  g_W2t[128*64];
__device__ float  g_W3t[128*128];
__device__ float  g_W4t[256*256];
__device__ float  g_W5t[512*1024];

// ---------------- helpers ----------------
__device__ __forceinline__ unsigned long long knn_key(float v, unsigned j) {
    int i = __float_as_int(v);
    unsigned u = (i >= 0) ? ((unsigned)i | 0x80000000u) : ~((unsigned)i);
    return ((unsigned long long)u << 32) | (unsigned long long)(0xFFFFFFFFu - j);
}
__device__ __forceinline__ float key_pd(unsigned long long k) {
    unsigned u = (unsigned)(k >> 32);
    int i = (u & 0x80000000u) ? (int)(u & 0x7FFFFFFFu) : (int)(~u);
    return __int_as_float(i);
}
__device__ __forceinline__ int key_idx(unsigned long long k) {
    return (int)(0xFFFFFFFFu - (unsigned)(k & 0xFFFFFFFFull));
}
__device__ __forceinline__ unsigned long long warp_max_bfly(unsigned long long v) {
    #pragma unroll
    for (int s = 16; s > 0; s >>= 1) {
        unsigned long long o = __shfl_xor_sync(0xFFFFFFFFu, v, s);
        v = (o > v) ? o : v;
    }
    return v;
}
__device__ __forceinline__ void atomicMaxFloat(float* addr, float val) {
    int* ia = (int*)addr;
    int old = *ia;
    while (__int_as_float(old) < val) {
        int assumed = old;
        old = atomicCAS(ia, assumed, __float_as_int(val));
        if (old == assumed) break;
    }
}
__device__ __forceinline__ void two_sum(float a, float b, float& s, float& e) {
    s = __fadd_rn(a, b);
    float bb = __fsub_rn(s, a);
    e = __fadd_rn(__fsub_rn(a, __fsub_rn(s, bb)), __fsub_rn(b, bb));
}
__device__ __forceinline__ void kah(float a, float b, float& sa, float& ca, float& ea) {
    float p = __fmul_rn(a, b);
    ea = __fadd_rn(ea, __fmaf_rn(a, b, -p));
    float y = __fsub_rn(p, ca);
    float t = __fadd_rn(sa, y);
    ca = __fsub_rn(__fsub_rn(t, sa), y);
    sa = t;
}
__device__ __forceinline__ float pd_tail(float H, float L, float2 xq, float2 xj) {
    float th = __fmul_rn(2.f, H), tl = __fmul_rn(2.f, L);
    float sA, eA;
    two_sum(th, -xq.x, sA, eA);
    eA = __fadd_rn(eA, __fsub_rn(tl, xq.y));
    float th2 = __fadd_rn(sA, eA);
    float tl2 = __fsub_rn(eA, __fsub_rn(th2, sA));
    float sB, eB;
    two_sum(th2, -xj.x, sB, eB);
    eB = __fadd_rn(eB, __fsub_rn(tl2, xj.y));
    return __fadd_rn(sB, eB);
}
__device__ __forceinline__ float pd_finalize(float s0, float s1, float s2, float s3,
                                             float c0, float c1, float c2, float c3,
                                             float e0, float e1, float e2, float e3,
                                             float2 xq, float2 xj) {
    float h01, l01, h23, l23, H, L;
    two_sum(s0, s1, h01, l01);
    two_sum(s2, s3, h23, l23);
    two_sum(h01, h23, H, L);
    float elo = __fadd_rn(__fadd_rn(__fadd_rn(e0, e1), __fadd_rn(e2, e3)),
                __fsub_rn(__fadd_rn(__fadd_rn(l01, l23), L),
                          __fadd_rn(__fadd_rn(c0, c1), __fadd_rn(c2, c3))));
    return pd_tail(H, elo, xq, xj);
}

// ---------------- transpose ----------------
__global__ void transpose_kernel(const float* __restrict__ in, float* __restrict__ out,
                                 int O, int I) {
    int idx = blockIdx.x * blockDim.x + threadIdx.x;
    if (idx >= O * I) return;
    int o = idx / I, c = idx % I;
    out[c * O + o] = in[idx];
}

// ---------------- reset kernels ----------------
__global__ void reset_stats_kernel() {
    int i = blockIdx.x * blockDim.x + threadIdx.x;
    if (i < 1024) { g_sum[i] = 0.0; g_sumsq[i] = 0.0; }
}
__global__ void reset_m5_kernel() {
    int i = blockIdx.x * blockDim.x + threadIdx.x;
    if (i < 1024) { g_sum[i] = 0.0; g_sumsq[i] = 0.0; }
    if (i < BB * 1024) g_m5[i] = -CUDART_INF_F;
}

// ---------------- BN fold ----------------
__global__ void bnparam_kernel(const float* __restrict__ gamma,
                               const float* __restrict__ beta, double Minv) {
    int o = threadIdx.x + blockIdx.x * blockDim.x;
    double mean = g_sum[o] * Minv;
    double var = g_sumsq[o] * Minv - mean * mean;
    double scale = 1.0 / sqrt(var + (double)EPSV);
    double A = (double)gamma[o] * scale;
    double B = (double)beta[o] - mean * A;
    g_bn[o] = make_float2((float)A, (float)B);
}

// ---------------- squared norms ----------------
template<int C>
__global__ void xx_kernel(const float* __restrict__ x) {
    int p = blockIdx.x * blockDim.x + threadIdx.x;
    if (p >= BN) return;
    const float* r = x + (size_t)p * C;
    double s = 0.0;
    #pragma unroll 4
    for (int c = 0; c < C; c++) { double v = (double)r[c]; s = fma(v, v, s); }
    float hi = (float)s;
    float lo = (float)(s - (double)hi);
    g_xx[p] = make_float2(hi, lo);
}

// ---------------- phase A: approx pd ----------------
template<int C>
__global__ __launch_bounds__(256) void pda_kernel(const float* __restrict__ x) {
    constexpr int CK = 64, CP = CK + 4;
    __shared__ __align__(16) float sQ[64][CP];
    __shared__ __align__(16) float sC[64][CP];
    const int tid = threadIdx.x;
    const int ty = tid >> 4, tx = tid & 15;
    const int b = blockIdx.z;
    const int q0 = blockIdx.x * 64;
    const int jt0 = blockIdx.y * 8;
    const float* xb = x + (size_t)b * NP * C;

    float xq[4];
    #pragma unroll
    for (int i = 0; i < 4; i++) xq[i] = g_xx[b * NP + q0 + ty * 4 + i].x;

    for (int jt = jt0; jt < jt0 + 8; jt++) {
        float acc[16];
        #pragma unroll
        for (int a = 0; a < 16; a++) acc[a] = 0.f;

        #pragma unroll
        for (int ch = 0; ch < C / CK; ch++) {
            __syncthreads();
            for (int idx = tid; idx < 64 * CK; idx += 256) {
                int row = idx >> 6, col = idx & 63;
                sQ[row][col] = xb[(size_t)(q0 + row) * C + ch * CK + col];
                sC[row][col] = xb[(size_t)(jt * 64 + row) * C + ch * CK + col];
            }
            __syncthreads();
            #pragma unroll 4
            for (int cc = 0; cc < CK; cc += 4) {
                float4 qv[4], cv[4];
                #pragma unroll
                for (int i = 0; i < 4; i++) {
                    qv[i] = *reinterpret_cast<const float4*>(&sQ[ty * 4 + i][cc]);
                    cv[i] = *reinterpret_cast<const float4*>(&sC[tx * 4 + i][cc]);
                }
                #pragma unroll
                for (int i = 0; i < 4; i++) {
                    #pragma unroll
                    for (int j2 = 0; j2 < 4; j2++) {
                        int a = i * 4 + j2;
                        acc[a] = __fmaf_rn(qv[i].x, cv[j2].x, acc[a]);
                        acc[a] = __fmaf_rn(qv[i].y, cv[j2].y, acc[a]);
                        acc[a] = __fmaf_rn(qv[i].z, cv[j2].z, acc[a]);
                        acc[a] = __fmaf_rn(qv[i].w, cv[j2].w, acc[a]);
                    }
                }
            }
        }
        #pragma unroll
        for (int j2 = 0; j2 < 4; j2++) {
            float xj = g_xx[b * NP + jt * 64 + tx * 4 + j2].x;
            #pragma unroll
            for (int i = 0; i < 4; i++) {
                float pd = (2.f * acc[i * 4 + j2] - xq[i]) - xj;
                g_pd[(size_t)(b * NP + q0 + ty * 4 + i) * NP + jt * 64 + tx * 4 + j2] = pd;
            }
        }
    }
}

// ---------------- phase B: select + refine ----------------
template<int C>
__global__ __launch_bounds__(256) void topk_refine_kernel(const float* __restrict__ x) {
    __shared__ unsigned long long swk[8][KK];
    __shared__ unsigned long long rkey[CAP];
    __shared__ int  cand[CAP];
    __shared__ int  scnt;
    __shared__ float sT;
    __shared__ __align__(16) float q[(C + 3) & ~3];
    const int tid = threadIdx.x;
    const int lane = tid & 31, warp = tid >> 5;
    const int pq = blockIdx.x;
    const int b = pq / NP, n = pq % NP;
    const float* xb = x + (size_t)b * NP * C;

    for (int c = tid; c < C; c += 256) q[c] = xb[(size_t)n * C + c];
    if (tid == 0) scnt = 0;
    if (tid < CAP) rkey[tid] = 0ULL;

    const float* pdrow = g_pd + (size_t)pq * NP;
    unsigned long long key[8];
    #pragma unroll
    for (int t = 0; t < 8; t++) {
        int j = tid + t * 256;
        key[t] = knn_key(pdrow[j], (unsigned)j);
    }
    #pragma unroll
    for (int a = 1; a < 8; a++) {
        unsigned long long kk = key[a];
        int p2 = a - 1;
        while (p2 >= 0 && key[p2] < kk) { key[p2 + 1] = key[p2]; p2--; }
        key[p2 + 1] = kk;
    }

    {
        int ptr = 0;
        #pragma unroll 1
        for (int sel = 0; sel < KK; sel++) {
            unsigned long long v = (ptr < 8) ? key[ptr] : 0ULL;
            unsigned long long m = warp_max_bfly(v);
            if (ptr < 8 && key[ptr] == m) ptr++;
            if (lane == 0) swk[warp][sel] = m;
        }
    }
    __syncthreads();

    if (warp == 0) {
        unsigned long long mk[5];
        #pragma unroll
        for (int i = 0; i < 5; i++) mk[i] = ((unsigned long long*)swk)[lane * 5 + i];
        unsigned long long m = 0;
        #pragma unroll 1
        for (int sel = 0; sel < KK; sel++) {
            unsigned long long lm = 0; int li = -1;
            #pragma unroll
            for (int i = 0; i < 5; i++) if (mk[i] > lm) { lm = mk[i]; li = i; }
            m = warp_max_bfly(lm);
            if (lm == m && li >= 0) mk[li] = 0ULL;
        }
        if (lane == 0) sT = key_pd(m) - DELTA;
    }
    __syncthreads();

    {
        float T = sT;
        #pragma unroll 1
        for (int t = 0; t < 8; t++) {
            if (key_pd(key[t]) < T) break;
            int pos = atomicAdd(&scnt, 1);
            if (pos < CAP) cand[pos] = key_idx(key[t]);
        }
    }
    __syncthreads();
    int cnt = min(scnt, CAP);

    float2 xq = g_xx[pq];
    if (tid < cnt) {
        int j = cand[tid];
        const float4* r4 = reinterpret_cast<const float4*>(xb + (size_t)j * C);
        const float4* q4 = reinterpret_cast<const float4*>(q);
        float s0 = 0.f, s1 = 0.f, s2 = 0.f, s3 = 0.f;
        float c0 = 0.f, c1 = 0.f, c2 = 0.f, c3 = 0.f;
        float e0 = 0.f, e1 = 0.f, e2 = 0.f, e3 = 0.f;
        #pragma unroll 4
        for (int c = 0; c < C / 4; c++) {
            float4 rv = r4[c], qv = q4[c];
            kah(qv.x, rv.x, s0, c0, e0);
            kah(qv.y, rv.y, s1, c1, e1);
            kah(qv.z, rv.z, s2, c2, e2);
            kah(qv.w, rv.w, s3, c3, e3);
        }
        float2 xj = g_xx[b * NP + j];
        float pd = pd_finalize(s0, s1, s2, s3, c0, c1, c2, c3, e0, e1, e2, e3, xq, xj);
        rkey[tid] = knn_key(pd, (unsigned)j);
    }
    __syncthreads();

    if (warp == 0) {
        unsigned long long mk[6];
        #pragma unroll
        for (int i = 0; i < 6; i++) mk[i] = rkey[lane * 6 + i];
        int* out = g_idx + (size_t)pq * KK;
        #pragma unroll 1
        for (int sel = 0; sel < KK; sel++) {
            unsigned long long lm = 0; int li = -1;
            #pragma unroll
            for (int i = 0; i < 6; i++) if (mk[i] > lm) { lm = mk[i]; li = i; }
            unsigned long long m = warp_max_bfly(lm);
            if (lm == m && li >= 0) mk[li] = 0ULL;
            if (lane == 0) out[sel] = key_idx(m);
        }
    }
}

// ---------------- layer-1 knn (C=3) ----------------
__global__ __launch_bounds__(256) void knn3_kernel(const float* __restrict__ x) {
    __shared__ unsigned long long swk[8][KK];
    const int tid = threadIdx.x;
    const int lane = tid & 31, warp = tid >> 5;
    const int b = blockIdx.x / NP;
    const int n = blockIdx.x % NP;
    const float* xb = x + (size_t)b * NP * 3;

    float q0 = xb[(size_t)n * 3 + 0], q1 = xb[(size_t)n * 3 + 1], q2 = xb[(size_t)n * 3 + 2];
    float2 xxi = g_xx[b * NP + n];
    const float2* xxb = g_xx + b * NP;

    unsigned long long key[8];
    #pragma unroll
    for (int t = 0; t < 8; t++) {
        int j = tid + t * 256;
        const float* r = xb + (size_t)j * 3;
        float r0 = r[0], r1 = r[1], r2 = r[2];
        float p0 = __fmul_rn(q0, r0), e0 = __fmaf_rn(q0, r0, -p0);
        float p1 = __fmul_rn(q1, r1), e1 = __fmaf_rn(q1, r1, -p1);
        float p2 = __fmul_rn(q2, r2), e2 = __fmaf_rn(q2, r2, -p2);
        float t1, u1, H, u2;
        two_sum(p0, p1, t1, u1);
        two_sum(t1, p2, H, u2);
        float L = __fadd_rn(__fadd_rn(__fadd_rn(e0, e1), e2), __fadd_rn(u1, u2));
        float pd = pd_tail(H, L, xxi, xxb[j]);
        key[t] = knn_key(pd, (unsigned)j);
    }
    #pragma unroll
    for (int a = 1; a < 8; a++) {
        unsigned long long kk = key[a];
        int p2 = a - 1;
        while (p2 >= 0 && key[p2] < kk) { key[p2 + 1] = key[p2]; p2--; }
        key[p2 + 1] = kk;
    }

    {
        int ptr = 0;
        #pragma unroll 1
        for (int sel = 0; sel < KK; sel++) {
            unsigned long long v = (ptr < 8) ? key[ptr] : 0ULL;
            unsigned long long m = warp_max_bfly(v);
            if (ptr < 8 && key[ptr] == m) ptr++;
            if (lane == 0) swk[warp][sel] = m;
        }
    }
    __syncthreads();

    if (warp == 0) {
        unsigned long long mk[5];
        #pragma unroll
        for (int i = 0; i < 5; i++) mk[i] = ((unsigned long long*)swk)[lane * 5 + i];
        int* out = g_idx + (size_t)(b * NP + n) * KK;
        #pragma unroll 1
        for (int sel = 0; sel < KK; sel++) {
            unsigned long long lm = 0; int li = -1;
            #pragma unroll
            for (int i = 0; i < 5; i++) if (mk[i] > lm) { lm = mk[i]; li = i; }
            unsigned long long m = warp_max_bfly(lm);
            if (lm == m && li >= 0) mk[li] = 0ULL;
            if (lane == 0) out[sel] = key_idx(m);
        }
    }
}

// ---------------- edge conv (R15 style): transposed weights, float4 D, fp32 stats ----------------
template<int C, int O, int TPB>
__global__ void conv_kernel(const float* __restrict__ xin, const float* __restrict__ Wt,
                            float* __restrict__ m) {
    __shared__ __align__(16) float xc[(C + 3) & ~3];
    __shared__ __align__(16) float D[KK][(C & 3) ? C + 1 : C + 4];
    __shared__ int nidx[KK];
    const int tid = threadIdx.x;
    const int b = blockIdx.x / NP;
    const int n = blockIdx.x % NP;
    const float* xb = xin + (size_t)b * NP * C;

    for (int c = tid; c < C; c += TPB) xc[c] = xb[(size_t)n * C + c];
    if (tid < KK) nidx[tid] = g_idx[(size_t)(b * NP + n) * KK + tid];
    __syncthreads();
    for (int e = tid; e < KK * C; e += TPB) {
        int k = e / C, c = e % C;
        D[k][c] = xb[(size_t)nidx[k] * C + c] - xc[c];
    }
    __syncthreads();

    for (int o = tid; o < O; o += TPB) {
        float cx = 0.f;
        #pragma unroll 4
        for (int c = 0; c < C; c++) cx += Wt[(C + c) * O + o] * xc[c];
        float acc[KK];
        #pragma unroll
        for (int k = 0; k < KK; k++) acc[k] = cx;
        if constexpr ((C & 3) == 0) {
            for (int c = 0; c < C; c += 4) {
                float w0 = Wt[(c + 0) * O + o];
                float w1 = Wt[(c + 1) * O + o];
                float w2 = Wt[(c + 2) * O + o];
                float w3 = Wt[(c + 3) * O + o];
                #pragma unroll
                for (int k = 0; k < KK; k++) {
                    float4 d = *reinterpret_cast<const float4*>(&D[k][c]);
                    acc[k] += w0 * d.x + w1 * d.y + w2 * d.z + w3 * d.w;
                }
            }
        } else {
            for (int c = 0; c < C; c++) {
                float w = Wt[c * O + o];
                #pragma unroll
                for (int k = 0; k < KK; k++) acc[k] += w * D[k][c];
            }
        }
        float mv = -CUDART_INF_F;
        float s = 0.f, s2 = 0.f;
        #pragma unroll
        for (int k = 0; k < KK; k++) {
            mv = fmaxf(mv, acc[k]);
            s = __fadd_rn(s, acc[k]);
            s2 = __fmaf_rn(acc[k], acc[k], s2);
        }
        m[(size_t)(b * NP + n) * O + o] = mv;
        atomicAdd(&g_sum[o], (double)s);
        atomicAdd(&g_sumsq[o], (double)s2);
    }
}

// ---------------- post: xout = lrelu(m*A + B) ----------------
template<int O>
__global__ void post_kernel(const float* __restrict__ m, float* __restrict__ xout) {
    int i = blockIdx.x * blockDim.x + threadIdx.x;
    if (i >= BN * O) return;
    int o = i % O;
    float2 ab = g_bn[o];
    float h = __fmaf_rn(m[i], ab.x, ab.y);
    xout[i] = (h >= 0.f) ? h : SLOPEV * h;
}

// ---------------- conv5: register-tiled (R16 version; validated) ----------------
// 16 points/block; thread: oi = tid>>2 (4 outputs per j-round), pi = tid&3 (4 points)
__global__ __launch_bounds__(256) void conv5_kernel() {
    constexpr int PP = 20;  // row stride 80B (16B-aligned), float4-clean at pi*4
    __shared__ __align__(16) float sxT[512][PP];
    const int tid = threadIdx.x;
    const int b = blockIdx.x / (NP / 16);
    const int n0 = (blockIdx.x % (NP / 16)) * 16;

    for (int e = tid; e < 16 * 512; e += 256) {
        int p = e >> 9, c = e & 511;
        size_t pn = (size_t)b * NP + n0 + p;
        float v;
        if (c < 64)       v = g_x1[pn * 64 + c];
        else if (c < 128) v = g_x2[pn * 64 + (c - 64)];
        else if (c < 256) v = g_x3[pn * 128 + (c - 128)];
        else              v = g_x4[pn * 256 + (c - 256)];
        sxT[c][p] = v;
    }
    __syncthreads();

    const int oi = tid >> 2, pi = tid & 3;

    #pragma unroll
    for (int j = 0; j < 4; j++) {
        int o0 = j * 256 + oi * 4;
        float acc[4][4];
        #pragma unroll
        for (int i = 0; i < 4; i++)
            #pragma unroll
            for (int p = 0; p < 4; p++) acc[i][p] = 0.f;

        for (int c = 0; c < 512; c++) {
            float4 w = *reinterpret_cast<const float4*>(g_W5t + (size_t)c * 1024 + o0);
            float4 d = *reinterpret_cast<const float4*>(&sxT[c][pi * 4]);
            acc[0][0] = __fmaf_rn(w.x, d.x, acc[0][0]);
            acc[0][1] = __fmaf_rn(w.x, d.y, acc[0][1]);
            acc[0][2] = __fmaf_rn(w.x, d.z, acc[0][2]);
            acc[0][3] = __fmaf_rn(w.x, d.w, acc[0][3]);
            acc[1][0] = __fmaf_rn(w.y, d.x, acc[1][0]);
            acc[1][1] = __fmaf_rn(w.y, d.y, acc[1][1]);
            acc[1][2] = __fmaf_rn(w.y, d.z, acc[1][2]);
            acc[1][3] = __fmaf_rn(w.y, d.w, acc[1][3]);
            acc[2][0] = __fmaf_rn(w.z, d.x, acc[2][0]);
            acc[2][1] = __fmaf_rn(w.z, d.y, acc[2][1]);
            acc[2][2] = __fmaf_rn(w.z, d.z, acc[2][2]);
            acc[2][3] = __fmaf_rn(w.z, d.w, acc[2][3]);
            acc[3][0] = __fmaf_rn(w.w, d.x, acc[3][0]);
            acc[3][1] = __fmaf_rn(w.w, d.y, acc[3][1]);
            acc[3][2] = __fmaf_rn(w.w, d.z, acc[3][2]);
            acc[3][3] = __fmaf_rn(w.w, d.w, acc[3][3]);
        }

        #pragma unroll
        for (int i = 0; i < 4; i++) {
            float mv = acc[i][0], s = acc[i][0], q = acc[i][0] * acc[i][0];
            #pragma unroll
            for (int p = 1; p < 4; p++) {
                mv = fmaxf(mv, acc[i][p]);
                s = __fadd_rn(s, acc[i][p]);
                q = __fmaf_rn(acc[i][p], acc[i][p], q);
            }
            #pragma unroll
            for (int sft = 1; sft <= 2; sft <<= 1) {
                mv = fmaxf(mv, __shfl_xor_sync(0xFFFFFFFFu, mv, sft));
                s  = __fadd_rn(s, __shfl_xor_sync(0xFFFFFFFFu, s, sft));
                q  = __fadd_rn(q, __shfl_xor_sync(0xFFFFFFFFu, q, sft));
            }
            if (pi == 0) {
                int o = o0 + i;
                atomicAdd(&g_sum[o], (double)s);
                atomicAdd(&g_sumsq[o], (double)q);
                atomicMaxFloat(&g_m5[b * 1024 + o], mv);
            }
        }
    }
}

// ---------------- final ----------------
__global__ void final_kernel(const float* __restrict__ g5, const float* __restrict__ b5,
                             float* __restrict__ out) {
    int b = blockIdx.x;
    int o = threadIdx.x;
    const double Minv = 1.0 / (double)(BB * NP);
    double mean = g_sum[o] * Minv;
    double var = g_sumsq[o] * Minv - mean * mean;
    float scale = (float)(1.0 / sqrt(var + (double)EPSV));
    float h = ((g_m5[b * 1024 + o] - (float)mean) * scale) * g5[o] + b5[o];
    out[b * 1024 + o] = (h >= 0.f) ? h : SLOPEV * h;
}

// ---------------- launch ----------------
extern "C" void kernel_launch(void* const* d_in, const int* in_sizes, int n_in,
                              void* d_out, int out_size) {
    const float* x  = (const float*)d_in[0];
    const float* W1 = (const float*)d_in[1];
    const float* g1 = (const float*)d_in[2];
    const float* b1 = (const float*)d_in[3];
    const float* W2 = (const float*)d_in[4];
    const float* g2 = (const float*)d_in[5];
    const float* b2 = (const float*)d_in[6];
    const float* W3 = (const float*)d_in[7];
    const float* g3 = (const float*)d_in[8];
    const float* b3 = (const float*)d_in[9];
    const float* W4 = (const float*)d_in[10];
    const float* g4 = (const float*)d_in[11];
    const float* b4 = (const float*)d_in[12];
    const float* W5 = (const float*)d_in[13];
    const float* g5 = (const float*)d_in[14];
    const float* b5 = (const float*)d_in[15];
    float* out = (float*)d_out;

    const double MinvK = 1.0 / (double)(BB * NP * KK);

    float *d_m, *d_x1, *d_x2, *d_x3, *d_x4;
    float *d_W1t, *d_W2t, *d_W3t, *d_W4t, *d_W5t;
    cudaGetSymbolAddress((void**)&d_m, g_m);
    cudaGetSymbolAddress((void**)&d_x1, g_x1);
    cudaGetSymbolAddress((void**)&d_x2, g_x2);
    cudaGetSymbolAddress((void**)&d_x3, g_x3);
    cudaGetSymbolAddress((void**)&d_x4, g_x4);
    cudaGetSymbolAddress((void**)&d_W1t, g_W1t);
    cudaGetSymbolAddress((void**)&d_W2t, g_W2t);
    cudaGetSymbolAddress((void**)&d_W3t, g_W3t);
    cudaGetSymbolAddress((void**)&d_W4t, g_W4t);
    cudaGetSymbolAddress((void**)&d_W5t, g_W5t);

    transpose_kernel<<<(64 * 6 + 255) / 256, 256>>>(W1, d_W1t, 64, 6);
    transpose_kernel<<<(64 * 128 + 255) / 256, 256>>>(W2, d_W2t, 64, 128);
    transpose_kernel<<<(128 * 128 + 255) / 256, 256>>>(W3, d_W3t, 128, 128);
    transpose_kernel<<<(256 * 256 + 255) / 256, 256>>>(W4, d_W4t, 256, 256);
    transpose_kernel<<<(1024 * 512 + 255) / 256, 256>>>(W5, d_W5t, 1024, 512);

    dim3 pdgrid(NP / 64, 4, BB);

    // ---- Layer 1 ----
    reset_stats_kernel<<<4, 256>>>();
    xx_kernel<3><<<BN / 256, 256>>>(x);
    knn3_kernel<<<BN, 256>>>(x);
    conv_kernel<3, 64, 128><<<BN, 128>>>(x, d_W1t, d_m);
    bnparam_kernel<<<1, 64>>>(g1, b1, MinvK);
    post_kernel<64><<<(BN * 64) / 256, 256>>>(d_m, d_x1);

    // ---- Layer 2 ----
    reset_stats_kernel<<<4, 256>>>();
    xx_kernel<64><<<BN / 256, 256>>>(d_x1);
    pda_kernel<64><<<pdgrid, 256>>>(d_x1);
    topk_refine_kernel<64><<<BN, 256>>>(d_x1);
    conv_kernel<64, 64, 128><<<BN, 128>>>(d_x1, d_W2t, d_m);
    bnparam_kernel<<<1, 64>>>(g2, b2, MinvK);
    post_kernel<64><<<(BN * 64) / 256, 256>>>(d_m, d_x2);

    // ---- Layer 3 ----
    reset_stats_kernel<<<4, 256>>>();
    xx_kernel<64><<<BN / 256, 256>>>(d_x2);
    pda_kernel<64><<<pdgrid, 256>>>(d_x2);
    topk_refine_kernel<64><<<BN, 256>>>(d_x2);
    conv_kernel<64, 128, 128><<<BN, 128>>>(d_x2, d_W3t, d_m);
    bnparam_kernel<<<1, 128>>>(g3, b3, MinvK);
    post_kernel<128><<<(BN * 128) / 256, 256>>>(d_m, d_x3);

    // ---- Layer 4 ----
    reset_stats_kernel<<<4, 256>>>();
    xx_kernel<128><<<BN / 256, 256>>>(d_x3);
    pda_kernel<128><<<pdgrid, 256>>>(d_x3);
    topk_refine_kernel<128><<<BN, 256>>>(d_x3);
    conv_kernel<128, 256, 256><<<BN, 256>>>(d_x3, d_W4t, d_m);
    bnparam_kernel<<<1, 256>>>(g4, b4, MinvK);
    post_kernel<256><<<(BN * 256) / 256, 256>>>(d_m, d_x4);

    // ---- conv5 + global max ----
    reset_m5_kernel<<<32, 256>>>();
    conv5_kernel<<<BB * (NP / 16), 256>>>();
    final_kernel<<<BB, 1024>>>(g5, b5, out);
}